// round 8
// baseline (speedup 1.0000x reference)
#include <cuda_runtime.h>
#include <math.h>

// Problem constants (fixed for this registry instance; B and L derived at launch)
constexpr int P_  = 4;     // num_pumps
constexpr int M_  = 4;     // modes
constexpr int C_  = 100;   // num_channels
constexpr int F_  = P_ + C_;      // 104 total frequencies
constexpr int SM_ = F_ * M_;      // 416 state elements
constexpr int GSTRIDE = 108;      // gain row stride (rows land on distinct bank quartets)

// 1e-3 * ln(10) / 10
#define ALPHA_LINF 2.3025850929940458e-4f
#define C0F 299792458.0f

struct ScalarPool {
    const void* p[8];
    int n;
};

__global__ __launch_bounds__(SM_, 3)
void raman_rk4_kernel(const float* __restrict__ x,          // (B, 20)
                      const float* __restrict__ sig_freq,   // (100,)
                      const float* __restrict__ buf400a,    // power or loss (400,)
                      const float* __restrict__ buf400b,    // the other one  (400,)
                      const float* __restrict__ loss_c,     // (3,) [quad, lin, const]
                      const float* __restrict__ ov,         // (4,4) symmetric
                      const float* __restrict__ raman,      // (L,)
                      ScalarPool sc,
                      float* __restrict__ out,              // (B, 100, 4)
                      int L)
{
    __shared__ __align__(16) float sGain[F_ * GSTRIDE];  // 44928 B
    __shared__ __align__(16) float sBufA[SM_];           //  1664 B stage vector (ping)
    __shared__ __align__(16) float sBufB[SM_];           //  1664 B stage vector (pong)
    __shared__ __align__(16) float sFreq[F_];            //   416 B

    const int b = blockIdx.x;
    const int t = threadIdx.x;                 // 0..415
    const float* xb = x + b * (P_ * (1 + M_)); // 20 floats per batch row

    // ---- resolve the two 400-element buffers by magnitude (power 1e-3 > loss 4.6e-5) ----
    const float* sig_pow  = (buf400a[0] >= buf400b[0]) ? buf400a : buf400b;
    const float* sig_loss = (buf400a[0] >= buf400b[0]) ? buf400b : buf400a;

    // ---- resolve scalars by VALUE from the pool of <=2-element inputs ----
    // Encodings seen in the wild: int32 (small int word) or float32 (word as float).
    // Value ranges are disjoint: steps~100 in (10,1e3); length~2e4 in [1e3,1e9];
    // max_freq~4e13 > 1e10. num_pumps/modes (=4) fall below 10 and are ignored.
    // (num_channels=100 collides with steps=100 -> same value, harmless.)
    float steps_v = 100.0f, length_v = 20000.0f, maxf_v = 4e13f;
    for (int k = 0; k < sc.n; ++k) {
        int iw = *(const int*)sc.p[k];
        float v;
        if (iw >= 2 && iw <= 1000000) {
            v = (float)iw;                       // plausible int32
        } else {
            float fw = __int_as_float(iw);       // else try float32
            if (!isfinite(fw) || fw < 1e-2f || fw > 1e17f) continue;
            v = fw;
        }
        if      (v > 1e10f)                 maxf_v   = v;
        else if (v >= 1e3f && v <= 1e9f)    length_v = v;
        else if (v > 10.0f)                 steps_v  = v;
    }
    const int   steps    = min(max((int)rintf(steps_v), 2), 20000);
    const float length   = length_v;
    const float max_freq = maxf_v;
    const float h  = length / (float)(steps - 1);
    const float hh = 0.5f * h;
    const float h6 = h / 6.0f;

    // ---- frequencies ----
    if (t < F_) {
        sFreq[t] = (t < P_) ? (C0F / xb[t]) : sig_freq[t - P_];
    }

    // ---- per-thread loss + initial power; state element t = (fidx, midx) ----
    const int fidx = t >> 2;    // frequency index 0..103 (pumps first)
    const int midx = t & 3;     // mode index
    float loss, y;
    if (fidx < P_) {
        float wl_nm = xb[fidx] * 1e9f;
        loss = (loss_c[2] + loss_c[1] * wl_nm + loss_c[0] * wl_nm * wl_nm) * ALPHA_LINF;
        y    = xb[P_ + t];                  // pump powers: x[:, num_pumps:]
    } else {
        loss = sig_loss[t - P_ * M_];
        y    = sig_pow [t - P_ * M_];
    }
    sBufA[t] = y;

    __syncthreads();   // sFreq (and sBufA) ready

    // ---- build gain matrix in SMEM: gain[i][j] at sGain[i*GSTRIDE + j] ----
    // gain[i][j] = sign(f_j - f_i) * raman_interp(|f_j - f_i|) * max(1, f_i/f_j)
    const float posscale = (float)(L - 1) / max_freq;
    for (int e = t; e < F_ * F_; e += SM_) {   // 10816 = 26 * 416
        int i = e / F_;
        int j = e - i * F_;
        float fi = sFreq[i], fj = sFreq[j];
        float fd = fj - fi;
        float pos = fabsf(fd) * posscale;
        int i0 = (int)floorf(pos);
        i0 = max(0, min(i0, L - 2));
        float w = pos - (float)i0;
        float g = __ldg(raman + i0) * (1.0f - w) + __ldg(raman + i0 + 1) * w;
        g = (fd < 0.0f) ? -g : g;                       // antisymmetric
        g *= fmaxf(1.0f, fi / fj);                      // photon-number scaling
        sGain[i * GSTRIDE + j] = g;
    }
    // visibility of sGain covered by the first EVAL barrier below

    // ---- per-thread constants for the direct row evaluation ----
    const float ov0 = ov[midx * 4 + 0], ov1 = ov[midx * 4 + 1];
    const float ov2 = ov[midx * 4 + 2], ov3 = ov[midx * 4 + 3];
    const float4* grow = (const float4*)(sGain + fidx * GSTRIDE);  // 432B stride, 16B aligned

    // EVAL: barrier, then r_t = sum_j gain[fidx][j] * sum_n ov[midx][n]*BUF[4j+n]
    //       k = (r - loss) * pstage
#define EVAL(KOUT, BUF, PSTAGE)                                                      \
    do {                                                                             \
        __syncthreads();                                                             \
        const float4* pv_ = (const float4*)(BUF);                                    \
        float acc_ = 0.0f;                                                           \
        _Pragma("unroll 13")                                                         \
        for (int j4 = 0; j4 < F_ / 4; ++j4) {                                        \
            float4 g4 = grow[j4];                                                    \
            float4 pa = pv_[4 * j4 + 0];                                             \
            float4 pb = pv_[4 * j4 + 1];                                             \
            float4 pc = pv_[4 * j4 + 2];                                             \
            float4 pd = pv_[4 * j4 + 3];                                             \
            float qa = fmaf(ov0, pa.x, fmaf(ov1, pa.y, fmaf(ov2, pa.z, ov3 * pa.w)));\
            float qb = fmaf(ov0, pb.x, fmaf(ov1, pb.y, fmaf(ov2, pb.z, ov3 * pb.w)));\
            float qc = fmaf(ov0, pc.x, fmaf(ov1, pc.y, fmaf(ov2, pc.z, ov3 * pc.w)));\
            float qd = fmaf(ov0, pd.x, fmaf(ov1, pd.y, fmaf(ov2, pd.z, ov3 * pd.w)));\
            acc_ = fmaf(g4.x, qa, acc_);                                             \
            acc_ = fmaf(g4.y, qb, acc_);                                             \
            acc_ = fmaf(g4.z, qc, acc_);                                             \
            acc_ = fmaf(g4.w, qd, acc_);                                             \
        }                                                                            \
        KOUT = (acc_ - loss) * (PSTAGE);                                             \
    } while (0)

    // ---- RK4 over z with ping-pong stage buffers (1 barrier per eval) ----
    // Safety: a buffer written after EVAL(kN) was last READ before kN's barrier,
    // so every write is separated from the prior reads by a full block barrier.
    for (int step = 0; step < steps - 1; ++step) {
        float k1, k2, k3, k4;
        EVAL(k1, sBufA, y);
        float p2 = fmaf(hh, k1, y);  sBufB[t] = p2;
        EVAL(k2, sBufB, p2);
        float p3 = fmaf(hh, k2, y);  sBufA[t] = p3;
        EVAL(k3, sBufA, p3);
        float p4 = fmaf(h,  k3, y);  sBufB[t] = p4;
        EVAL(k4, sBufB, p4);
        y = fmaf(h6, k1 + 2.0f * k2 + 2.0f * k3 + k4, y);
        sBufA[t] = y;
    }

    // ---- emit signal spectrum: out[b, c, m] for f >= num_pumps ----
    if (fidx >= P_) {
        out[b * (C_ * M_) + (t - P_ * M_)] = y;
    }
}

extern "C" void kernel_launch(void* const* d_in, const int* in_sizes, int n_in,
                              void* d_out, int out_size)
{
    // ---- order-independent input identification by element count ----
    // Expected sizes: x = B*20 (largest), sig_freq = 100, power/loss = 400 each,
    // loss_coefficients = 3, overlap = 16, raman = ~801, scalars = 1.
    int ix = -1, isf = -1, i4a = -1, i4b = -1, ilc = -1, iov = -1, irr = -1;
    ScalarPool sc; sc.n = 0;

    int largest = 0;
    for (int i = 1; i < n_in; ++i)
        if (in_sizes[i] > in_sizes[largest]) largest = i;

    for (int i = 0; i < n_in; ++i) {
        if (i == largest)                { ix = i; continue; }
        int sz = in_sizes[i];
        if      (sz == 100)              isf = i;
        else if (sz == 400)              { if (i4a < 0) i4a = i; else i4b = i; }
        else if (sz == 3)                ilc = i;
        else if (sz == 16)               iov = i;
        else if (sz <= 2)                { if (sc.n < 8) sc.p[sc.n++] = d_in[i]; }
        else                             irr = i;   // raman response (801)
    }

    const float* x        = (const float*)d_in[ix];
    const float* sig_freq = (const float*)d_in[isf];
    const float* b400a    = (const float*)d_in[i4a];
    const float* b400b    = (const float*)d_in[i4b];
    const float* loss_c   = (const float*)d_in[ilc];
    const float* ov       = (const float*)d_in[iov];
    const float* raman    = (const float*)d_in[irr];

    const int B = in_sizes[ix] / (P_ * (1 + M_));   // x is (B, 20)
    const int L = in_sizes[irr];                    // raman_response length

    raman_rk4_kernel<<<B, SM_>>>(x, sig_freq, b400a, b400b, loss_c, ov, raman,
                                 sc, (float*)d_out, L);
}

// round 9
// speedup vs baseline: 1.8843x; 1.8843x over previous
#include <cuda_runtime.h>
#include <math.h>

// Problem constants (fixed for this registry instance; B and L derived at launch)
constexpr int P_  = 4;     // num_pumps
constexpr int M_  = 4;     // modes
constexpr int C_  = 100;   // num_channels
constexpr int F_  = P_ + C_;      // 104 total frequencies
constexpr int SM_ = F_ * M_;      // 416 state elements
constexpr int GSTRIDE = 108;      // gain row stride: rows land on distinct bank quartets
constexpr int QSTRIDE = 108;      // Qt rows: same trick

// 1e-3 * ln(10) / 10
#define ALPHA_LINF 2.3025850929940458e-4f
#define C0F 299792458.0f

struct ScalarPool {
    const void* p[8];
    int n;
};

// Packed dual-FMA (Blackwell f32x2; one SASS FFMA2, 2 MACs/inst)
__device__ __forceinline__ unsigned long long fma_f32x2(
    unsigned long long a, unsigned long long b, unsigned long long c)
{
    unsigned long long d;
    asm("fma.rn.f32x2 %0, %1, %2, %3;" : "=l"(d) : "l"(a), "l"(b), "l"(c));
    return d;
}
__device__ __forceinline__ float2 unpack_f32x2(unsigned long long v)
{
    float2 r;
    asm("mov.b64 {%0, %1}, %2;" : "=f"(r.x), "=f"(r.y) : "l"(v));
    return r;
}

__global__ __launch_bounds__(SM_, 3)
void raman_rk4_kernel(const float* __restrict__ x,          // (B, 20)
                      const float* __restrict__ sig_freq,   // (100,)
                      const float* __restrict__ buf400a,    // power or loss (400,)
                      const float* __restrict__ buf400b,    // the other one  (400,)
                      const float* __restrict__ loss_c,     // (3,) [quad, lin, const]
                      const float* __restrict__ ov,         // (4,4) symmetric
                      const float* __restrict__ raman,      // (L,)
                      ScalarPool sc,
                      float* __restrict__ out,              // (B, 100, 4)
                      int L)
{
    __shared__ __align__(16) float sGain[F_ * GSTRIDE];   // 44928 B
    __shared__ __align__(16) float sQt[2][M_ * QSTRIDE];  //  3456 B  ping-pong Q[m][j]
    __shared__ __align__(16) float sFreq[F_];             //   416 B

    const int b = blockIdx.x;
    const int t = threadIdx.x;                 // 0..415 (13 full warps)
    const float* xb = x + b * (P_ * (1 + M_)); // 20 floats per batch row

    // ---- resolve the two 400-element buffers by magnitude (power 1e-3 > loss 4.6e-5) ----
    const float* sig_pow  = (buf400a[0] >= buf400b[0]) ? buf400a : buf400b;
    const float* sig_loss = (buf400a[0] >= buf400b[0]) ? buf400b : buf400a;

    // ---- resolve scalars by VALUE from the pool of <=2-element inputs ----
    // steps~100 in (10,1e3); length~2e4 in [1e3,1e9]; max_freq~4e13 > 1e10.
    float steps_v = 100.0f, length_v = 20000.0f, maxf_v = 4e13f;
    for (int k = 0; k < sc.n; ++k) {
        int iw = *(const int*)sc.p[k];
        float v;
        if (iw >= 2 && iw <= 1000000) {
            v = (float)iw;                       // plausible int32
        } else {
            float fw = __int_as_float(iw);       // else try float32
            if (!isfinite(fw) || fw < 1e-2f || fw > 1e17f) continue;
            v = fw;
        }
        if      (v > 1e10f)                 maxf_v   = v;
        else if (v >= 1e3f && v <= 1e9f)    length_v = v;
        else if (v > 10.0f)                 steps_v  = v;
    }
    const int   steps    = min(max((int)rintf(steps_v), 2), 20000);
    const float length   = length_v;
    const float max_freq = maxf_v;
    const float h  = length / (float)(steps - 1);
    const float hh = 0.5f * h;
    const float h6 = h / 6.0f;

    // ---- frequencies ----
    if (t < F_) {
        sFreq[t] = (t < P_) ? (C0F / xb[t]) : sig_freq[t - P_];
    }

    // ---- per-thread loss + initial power; state element t = (fidx, midx) ----
    const int fidx = t >> 2;    // frequency index 0..103 (pumps first)
    const int midx = t & 3;     // mode index
    float loss, y;
    if (fidx < P_) {
        float wl_nm = xb[fidx] * 1e9f;
        loss = (loss_c[2] + loss_c[1] * wl_nm + loss_c[0] * wl_nm * wl_nm) * ALPHA_LINF;
        y    = xb[P_ + t];                  // pump powers: x[:, num_pumps:]
    } else {
        loss = sig_loss[t - P_ * M_];
        y    = sig_pow [t - P_ * M_];
    }

    __syncthreads();   // sFreq ready

    // ---- build gain matrix in SMEM: gain[i][j] at sGain[i*GSTRIDE + j] ----
    const float posscale = (float)(L - 1) / max_freq;
    for (int e = t; e < F_ * F_; e += SM_) {   // 10816 = 26 * 416
        int i = e / F_;
        int j = e - i * F_;
        float fi = sFreq[i], fj = sFreq[j];
        float fd = fj - fi;
        float pos = fabsf(fd) * posscale;
        int i0 = (int)floorf(pos);
        i0 = max(0, min(i0, L - 2));
        float w = pos - (float)i0;
        float g = __ldg(raman + i0) * (1.0f - w) + __ldg(raman + i0 + 1) * w;
        g = (fd < 0.0f) ? -g : g;                       // antisymmetric
        g *= fmaxf(1.0f, fi / fj);                      // photon-number scaling
        sGain[i * GSTRIDE + j] = g;
    }
    // sGain visibility: covered by the first EVAL's barrier

    // ---- per-thread constants ----
    // Permuted overlap coefficients: coefficient for the value shuffled from
    // lane midx^k is ov[midx][midx^k].
    const float c0 = ov[midx * 4 + midx];
    const float c1 = ov[midx * 4 + (midx ^ 1)];
    const float c2 = ov[midx * 4 + (midx ^ 2)];
    const float c3 = ov[midx * 4 + (midx ^ 3)];

    // Row pointers as packed-f32x2 pairs (rows are 432 B apart -> 16B-aligned)
    const ulonglong2* g2p  = (const ulonglong2*)(sGain + fidx * GSTRIDE);   // 26 entries
    const ulonglong2* q2p0 = (const ulonglong2*)(sQt[0] + midx * QSTRIDE);
    const ulonglong2* q2p1 = (const ulonglong2*)(sQt[1] + midx * QSTRIDE);
    float* qw0 = &sQt[0][midx * QSTRIDE + fidx];
    float* qw1 = &sQt[1][midx * QSTRIDE + fidx];

    // EVAL: quad-exchange Q via shfl, one barrier, packed-FMA dot.
    //   Q[fidx,midx] = sum_n ov[midx][n] * Pquad[n]   (quad = lanes t&~3 .. t|3)
    //   r_t = sum_j gain[fidx][j] * Q[j,midx];  k = (r - loss) * pstage
#define EVAL(KOUT, QW, QR, PSTAGE)                                                   \
    do {                                                                             \
        float p_  = (PSTAGE);                                                        \
        float pa_ = __shfl_xor_sync(0xffffffffu, p_, 1);                             \
        float pb_ = __shfl_xor_sync(0xffffffffu, p_, 2);                             \
        float pc_ = __shfl_xor_sync(0xffffffffu, p_, 3);                             \
        *(QW) = fmaf(c0, p_, fmaf(c1, pa_, fmaf(c2, pb_, c3 * pc_)));                \
        __syncthreads();                                                             \
        unsigned long long a0 = 0ull, a1 = 0ull, a2 = 0ull, a3 = 0ull;               \
        _Pragma("unroll")                                                            \
        for (int j = 0; j < 13; ++j) {                                               \
            ulonglong2 ga = g2p[2 * j];                                              \
            ulonglong2 gb = g2p[2 * j + 1];                                          \
            ulonglong2 qa = (QR)[2 * j];                                             \
            ulonglong2 qb = (QR)[2 * j + 1];                                         \
            a0 = fma_f32x2(ga.x, qa.x, a0);                                          \
            a1 = fma_f32x2(ga.y, qa.y, a1);                                          \
            a2 = fma_f32x2(gb.x, qb.x, a2);                                          \
            a3 = fma_f32x2(gb.y, qb.y, a3);                                          \
        }                                                                            \
        float2 u0 = unpack_f32x2(a0), u1 = unpack_f32x2(a1);                         \
        float2 u2 = unpack_f32x2(a2), u3 = unpack_f32x2(a3);                         \
        float r_ = ((u0.x + u0.y) + (u1.x + u1.y))                                   \
                 + ((u2.x + u2.y) + (u3.x + u3.y));                                  \
        KOUT = (r_ - loss) * p_;                                                     \
    } while (0)

    // ---- RK4 over z; ping-pong sQt, ONE barrier per eval ----
    // Hazard check: a write to buffer X is always separated from X's previous
    // readers by the intervening eval's barrier (buffers alternate 0,1,0,1).
    for (int step = 0; step < steps - 1; ++step) {
        float k1, k2, k3, k4;
        EVAL(k1, qw0, q2p0, y);
        float p2 = fmaf(hh, k1, y);
        EVAL(k2, qw1, q2p1, p2);
        float p3 = fmaf(hh, k2, y);
        EVAL(k3, qw0, q2p0, p3);
        float p4 = fmaf(h,  k3, y);
        EVAL(k4, qw1, q2p1, p4);
        y = fmaf(h6, k1 + 2.0f * k2 + 2.0f * k3 + k4, y);
    }

    // ---- emit signal spectrum: out[b, c, m] for f >= num_pumps ----
    if (fidx >= P_) {
        out[b * (C_ * M_) + (t - P_ * M_)] = y;
    }
}

extern "C" void kernel_launch(void* const* d_in, const int* in_sizes, int n_in,
                              void* d_out, int out_size)
{
    // ---- order-independent input identification by element count ----
    int ix = -1, isf = -1, i4a = -1, i4b = -1, ilc = -1, iov = -1, irr = -1;
    ScalarPool sc; sc.n = 0;

    int largest = 0;
    for (int i = 1; i < n_in; ++i)
        if (in_sizes[i] > in_sizes[largest]) largest = i;

    for (int i = 0; i < n_in; ++i) {
        if (i == largest)                { ix = i; continue; }
        int sz = in_sizes[i];
        if      (sz == 100)              isf = i;
        else if (sz == 400)              { if (i4a < 0) i4a = i; else i4b = i; }
        else if (sz == 3)                ilc = i;
        else if (sz == 16)               iov = i;
        else if (sz <= 2)                { if (sc.n < 8) sc.p[sc.n++] = d_in[i]; }
        else                             irr = i;   // raman response (~801)
    }

    const float* x        = (const float*)d_in[ix];
    const float* sig_freq = (const float*)d_in[isf];
    const float* b400a    = (const float*)d_in[i4a];
    const float* b400b    = (const float*)d_in[i4b];
    const float* loss_c   = (const float*)d_in[ilc];
    const float* ov       = (const float*)d_in[iov];
    const float* raman    = (const float*)d_in[irr];

    const int B = in_sizes[ix] / (P_ * (1 + M_));   // x is (B, 20)
    const int L = in_sizes[irr];                    // raman_response length

    raman_rk4_kernel<<<B, SM_>>>(x, sig_freq, b400a, b400b, loss_c, ov, raman,
                                 sc, (float*)d_out, L);
}

// round 10
// speedup vs baseline: 4.8607x; 2.5795x over previous
#include <cuda_runtime.h>
#include <math.h>

// Problem constants (fixed for this registry instance; B and L derived at launch)
constexpr int P_  = 4;     // num_pumps
constexpr int M_  = 4;     // modes
constexpr int C_  = 100;   // num_channels
constexpr int F_  = P_ + C_;      // 104 total frequencies
constexpr int SM_ = F_ * M_;      // 416 threads
constexpr int GS  = 104;   // gain row stride during build (one-time, conflicts OK)
constexpr int QS  = 136;   // Qt row stride: 136 mod 32 = 8 -> u64 reads conflict-free

// 1e-3 * ln(10) / 10
#define ALPHA_LINF 2.3025850929940458e-4f
#define C0F 299792458.0f

struct ScalarPool {
    const void* p[8];
    int n;
};

// Packed dual-FMA (Blackwell f32x2 -> one SASS FFMA2, 2 MACs/inst)
__device__ __forceinline__ unsigned long long fma2(
    unsigned long long a, unsigned long long b, unsigned long long c)
{
    unsigned long long d;
    asm("fma.rn.f32x2 %0, %1, %2, %3;" : "=l"(d) : "l"(a), "l"(b), "l"(c));
    return d;
}
__device__ __forceinline__ float2 unpk(unsigned long long v)
{
    float2 r;
    asm("mov.b64 {%0, %1}, %2;" : "=f"(r.x), "=f"(r.y) : "l"(v));
    return r;
}

__global__ __launch_bounds__(SM_, 1)
void raman_rk4_kernel(const float* __restrict__ x,          // (B, 20)
                      const float* __restrict__ sig_freq,   // (100,)
                      const float* __restrict__ buf400a,    // power or loss (400,)
                      const float* __restrict__ buf400b,    // the other one  (400,)
                      const float* __restrict__ loss_c,     // (3,) [quad, lin, const]
                      const float* __restrict__ ov,         // (4,4) symmetric
                      const float* __restrict__ raman,      // (L,)
                      ScalarPool sc,
                      float* __restrict__ out,              // (B, 100, 4)
                      int L)
{
    // Pool: first holds the 104x104 gain matrix (43264 B) during build;
    // after rows are copied to registers it is reused for the ping-pong Qt.
    __shared__ __align__(16) float sPool[F_ * GS];
    __shared__ __align__(16) float sFreq[F_];

    const int b = blockIdx.x;
    const int t = threadIdx.x;                 // 0..415, 13 full warps
    const float* xb = x + b * (P_ * (1 + M_)); // 20 floats per batch row

    // Thread coordinates: t = fq*16 + jq*4 + m
    const int m  = t & 3;          // mode
    const int jq = (t >> 2) & 3;   // j-quarter (and owned-row group)
    const int fq = t >> 4;         // 0..25
    const int rown = fq + 26 * jq; // owned frequency row (0..103)

    // ---- resolve the two 400-element buffers by magnitude (power 1e-3 > loss 4.6e-5) ----
    const float* sig_pow  = (buf400a[0] >= buf400b[0]) ? buf400a : buf400b;
    const float* sig_loss = (buf400a[0] >= buf400b[0]) ? buf400b : buf400a;

    // ---- resolve scalars by VALUE from the pool of <=2-element inputs ----
    float steps_v = 100.0f, length_v = 20000.0f, maxf_v = 4e13f;
    for (int k = 0; k < sc.n; ++k) {
        int iw = *(const int*)sc.p[k];
        float v;
        if (iw >= 2 && iw <= 1000000) {
            v = (float)iw;                       // plausible int32
        } else {
            float fw = __int_as_float(iw);       // else try float32
            if (!isfinite(fw) || fw < 1e-2f || fw > 1e17f) continue;
            v = fw;
        }
        if      (v > 1e10f)                 maxf_v   = v;
        else if (v >= 1e3f && v <= 1e9f)    length_v = v;
        else if (v > 10.0f)                 steps_v  = v;
    }
    const int   steps    = min(max((int)rintf(steps_v), 2), 20000);
    const float length   = length_v;
    const float max_freq = maxf_v;
    const float h  = length / (float)(steps - 1);
    const float hh = 0.5f * h;
    const float h6 = h / 6.0f;

    // ---- frequencies ----
    if (t < F_) {
        sFreq[t] = (t < P_) ? (C0F / xb[t]) : sig_freq[t - P_];
    }

    // ---- per-thread loss + initial power for state element (rown, m) ----
    const int e = rown * 4 + m;
    float loss, y;
    if (rown < P_) {
        float wl_nm = xb[rown] * 1e9f;
        loss = (loss_c[2] + loss_c[1] * wl_nm + loss_c[0] * wl_nm * wl_nm) * ALPHA_LINF;
        y    = xb[P_ + e];                  // pump powers: x[:, num_pumps:]
    } else {
        loss = sig_loss[e - P_ * M_];
        y    = sig_pow [e - P_ * M_];
    }

    __syncthreads();   // sFreq ready

    // ---- build gain matrix into sPool: gain[i][j] at sPool[i*GS + j] ----
    const float posscale = (float)(L - 1) / max_freq;
    for (int ee = t; ee < F_ * F_; ee += SM_) {
        int i = ee / F_;
        int j = ee - i * F_;
        float fi = sFreq[i], fj = sFreq[j];
        float fd = fj - fi;
        float pos = fabsf(fd) * posscale;
        int i0 = (int)floorf(pos);
        i0 = max(0, min(i0, L - 2));
        float w = pos - (float)i0;
        float g = __ldg(raman + i0) * (1.0f - w) + __ldg(raman + i0 + 1) * w;
        g = (fd < 0.0f) ? -g : g;                       // antisymmetric
        g *= fmaxf(1.0f, fi / fj);                      // photon-number scaling
        sPool[i * GS + j] = g;
    }
    __syncthreads();   // gain complete

    // ---- copy this thread's 4 gain rows x 13 f32x2-pairs into registers ----
    // rows {fq, fq+26, fq+52, fq+78}, columns [26*jq, 26*jq+26)
    unsigned long long greg[52];
#pragma unroll
    for (int k = 0; k < 4; ++k) {
        const unsigned long long* src =
            (const unsigned long long*)(sPool + (fq + 26 * k) * GS + 26 * jq);
#pragma unroll
        for (int w = 0; w < 13; ++w) greg[k * 13 + w] = src[w];
    }
    __syncthreads();   // everyone done reading gain -> pool becomes Qt

    // ---- Qt ping-pong views inside the pool: Qt[buf][m][j], stride QS ----
    float* qt0 = sPool;            // 4*136 floats
    float* qt1 = sPool + 4 * QS;
    float* qw0 = qt0 + m * QS + rown;   // this thread's Q write slot
    float* qw1 = qt1 + m * QS + rown;
    const unsigned long long* qr0 = (const unsigned long long*)(qt0 + m * QS + 26 * jq);
    const unsigned long long* qr1 = (const unsigned long long*)(qt1 + m * QS + 26 * jq);

    // Overlap coefficients permuted for quad shfl_xor (value from lane m^k gets ov[m][m^k])
    const float c0 = ov[m * 4 + m];
    const float c1 = ov[m * 4 + (m ^ 1)];
    const float c2 = ov[m * 4 + (m ^ 2)];
    const float c3 = ov[m * 4 + (m ^ 3)];
    const bool jq1 = (jq & 1) != 0;
    const bool jq2 = (jq & 2) != 0;

    // EVAL:
    //  1) quad shfl -> Q[rown][m] written to Qt      (3 shfl + 4 FMA + 1 STS)
    //  2) barrier
    //  3) 13 u64 Q loads feed 4 register gain rows   (13 LDS.64 + 52 FFMA2)
    //  4) reduce-scatter partials across jq lanes    (3 shfl) -> own row sum
#define EVAL(KOUT, QW, QR, PST)                                                      \
    do {                                                                             \
        float p_  = (PST);                                                           \
        float pa_ = __shfl_xor_sync(0xffffffffu, p_, 1);                             \
        float pb_ = __shfl_xor_sync(0xffffffffu, p_, 2);                             \
        float pc_ = __shfl_xor_sync(0xffffffffu, p_, 3);                             \
        *(QW) = fmaf(c0, p_, fmaf(c1, pa_, fmaf(c2, pb_, c3 * pc_)));                \
        __syncthreads();                                                             \
        unsigned long long a0 = 0ull, a1 = 0ull, a2 = 0ull, a3 = 0ull;               \
        _Pragma("unroll")                                                            \
        for (int w = 0; w < 13; ++w) {                                               \
            unsigned long long q_ = (QR)[w];                                         \
            a0 = fma2(greg[w],      q_, a0);                                         \
            a1 = fma2(greg[13 + w], q_, a1);                                         \
            a2 = fma2(greg[26 + w], q_, a2);                                         \
            a3 = fma2(greg[39 + w], q_, a3);                                         \
        }                                                                            \
        float2 u0 = unpk(a0), u1 = unpk(a1), u2 = unpk(a2), u3 = unpk(a3);           \
        float s0 = u0.x + u0.y, s1 = u1.x + u1.y;                                    \
        float s2 = u2.x + u2.y, s3 = u3.x + u3.y;                                    \
        float vA = jq1 ? s0 : s1;                                                    \
        float rA = __shfl_xor_sync(0xffffffffu, vA, 4);                              \
        float vB = jq1 ? s2 : s3;                                                    \
        float rB = __shfl_xor_sync(0xffffffffu, vB, 4);                              \
        float aa = (jq1 ? s1 : s0) + rA;                                             \
        float bb = (jq1 ? s3 : s2) + rB;                                             \
        float vC = jq2 ? aa : bb;                                                    \
        float rC = __shfl_xor_sync(0xffffffffu, vC, 8);                              \
        float r_ = (jq2 ? bb : aa) + rC;                                             \
        KOUT = (r_ - loss) * p_;                                                     \
    } while (0)

    // ---- RK4 over z; ping-pong Qt, one barrier per eval ----
    // Write to buf X (pre-barrier of eval N) is separated from buf X's readers
    // (post-barrier of eval N-2) by eval N-1's barrier.
    for (int step = 0; step < steps - 1; ++step) {
        float k1, k2, k3, k4;
        EVAL(k1, qw0, qr0, y);
        float p2 = fmaf(hh, k1, y);
        EVAL(k2, qw1, qr1, p2);
        float p3 = fmaf(hh, k2, y);
        EVAL(k3, qw0, qr0, p3);
        float p4 = fmaf(h,  k3, y);
        EVAL(k4, qw1, qr1, p4);
        y = fmaf(h6, k1 + 2.0f * k2 + 2.0f * k3 + k4, y);
    }

    // ---- emit signal spectrum: out[b, c, m] for rows >= num_pumps ----
    if (rown >= P_) {
        out[b * (C_ * M_) + (e - P_ * M_)] = y;
    }
}

extern "C" void kernel_launch(void* const* d_in, const int* in_sizes, int n_in,
                              void* d_out, int out_size)
{
    // ---- order-independent input identification by element count ----
    int ix = -1, isf = -1, i4a = -1, i4b = -1, ilc = -1, iov = -1, irr = -1;
    ScalarPool sc; sc.n = 0;

    int largest = 0;
    for (int i = 1; i < n_in; ++i)
        if (in_sizes[i] > in_sizes[largest]) largest = i;

    for (int i = 0; i < n_in; ++i) {
        if (i == largest)                { ix = i; continue; }
        int sz = in_sizes[i];
        if      (sz == 100)              isf = i;
        else if (sz == 400)              { if (i4a < 0) i4a = i; else i4b = i; }
        else if (sz == 3)                ilc = i;
        else if (sz == 16)               iov = i;
        else if (sz <= 2)                { if (sc.n < 8) sc.p[sc.n++] = d_in[i]; }
        else                             irr = i;   // raman response (~801)
    }

    const float* x        = (const float*)d_in[ix];
    const float* sig_freq = (const float*)d_in[isf];
    const float* b400a    = (const float*)d_in[i4a];
    const float* b400b    = (const float*)d_in[i4b];
    const float* loss_c   = (const float*)d_in[ilc];
    const float* ov       = (const float*)d_in[iov];
    const float* raman    = (const float*)d_in[irr];

    const int B = in_sizes[ix] / (P_ * (1 + M_));   // x is (B, 20)
    const int L = in_sizes[irr];                    // raman_response length

    raman_rk4_kernel<<<B, SM_>>>(x, sig_freq, b400a, b400b, loss_c, ov, raman,
                                 sc, (float*)d_out, L);
}